// round 3
// baseline (speedup 1.0000x reference)
#include <cuda_runtime.h>
#include <cstdint>
#include <cstddef>

#define HID 1024
#define NB 128        // batch
#define TSTEPS 256
#define HORIZON 24

// ---------------- persistent scratch (__device__ globals; no allocs) -------------
__device__ float g_ys0[(size_t)TSTEPS * NB * HID];   // encoder layer0 outputs (134 MB)
__device__ float g_hB[2 * NB * HID];                 // enc layer1 h ping-pong
__device__ float g_hd0[2 * NB * HID];                // dec layer0 h ping-pong
__device__ float g_hd1[2 * NB * HID];                // dec layer1 h ping-pong
__device__ float g_c0[NB * HID];
__device__ float g_c1[NB * HID];
__device__ float g_zero[NB * HID];
__device__ float g_xpad[TSTEPS * NB * 16];           // x staged to 16-wide, zero padded
__device__ float g_predpad[NB * 16];                 // decoder scalar input, padded

// ---------------- helpers --------------------------------------------------------
// tf32 round: PTX cvt.rna.tf32.f32 requires a .b32 destination register.
__device__ __forceinline__ float rn_tf32(float x) {
  uint32_t r;
  asm("cvt.rna.tf32.f32 %0, %1;" : "=r"(r) : "f"(x));
  return __uint_as_float(r);
}

__device__ __forceinline__ void mma_tf32(float d[4], const uint32_t a[4], const uint32_t b[2]) {
  asm volatile(
      "mma.sync.aligned.m16n8k8.row.col.f32.tf32.tf32.f32 "
      "{%0,%1,%2,%3}, {%4,%5,%6,%7}, {%8,%9}, {%0,%1,%2,%3};\n"
      : "+f"(d[0]), "+f"(d[1]), "+f"(d[2]), "+f"(d[3])
      : "r"(a[0]), "r"(a[1]), "r"(a[2]), "r"(a[3]), "r"(b[0]), "r"(b[1]));
}

__device__ __forceinline__ float sigmoidf_(float x) { return 1.f / (1.f + expf(-x)); }

// ---------------- fused LSTM step: gates GEMM + pointwise ------------------------
// 3xTF32 precision: operands split hi/lo, acc += ah*bh + ah*bl + al*bh.
// gates[m, c] = sum_k A[m,k] * W'[c,k] + b'[c],   c = 4*j + g  (gate-interleaved)
// A = [Ax (KxPad cols, zero padded past Kx) | Ah (1024 cols)]
// W'[4j+g, k] = k < KxPad ? (k < Kx ? Wih[g*H+j, k] : 0) : Whh[g*H+j, k-KxPad]
// CTA: 128 threads, tile M=64 x N=64, warps 2x2 (warp tile 32x32), K-chunk 16.
__global__ void __launch_bounds__(128) lstm_step_kernel(
    const float* __restrict__ Ax, int axStride, int Kx, int KxPad,
    const float* __restrict__ Ah,
    const float* __restrict__ Wih, const float* __restrict__ Whh,
    const float* __restrict__ bias,
    float* __restrict__ cState, float* __restrict__ hOut)
{
  __shared__ __align__(16) float AsH[64][20];
  __shared__ __align__(16) float AsL[64][20];
  __shared__ __align__(16) float BsH[64][20];
  __shared__ __align__(16) float BsL[64][20];

  const int tid  = threadIdx.x;
  const int lane = tid & 31;
  const int wid  = tid >> 5;
  const int wm   = wid >> 1;        // warp row (0..1)
  const int wn   = wid & 1;         // warp col (0..1)
  const int gid  = lane >> 2;       // group id 0..7
  const int q    = lane & 3;        // thread-in-group
  const int mBase = blockIdx.y * 64;
  const int nBase = blockIdx.x * 64;
  const int iters = (KxPad + HID) >> 4;

  const int rowLd = tid >> 1;             // 0..63
  const int kb    = (tid & 1) * 8;        // 0 or 8
  const int mG    = mBase + rowLd;
  const int nG    = nBase + rowLd;
  const size_t origRow = (size_t)(nG & 3) * HID + (nG >> 2);

  float fa[8], fb[8];

#define LOAD_CHUNK(IT)                                                                 \
  do {                                                                                 \
    const int k0_ = (IT) * 16 + kb;                                                    \
    _Pragma("unroll")                                                                  \
    for (int h_ = 0; h_ < 2; ++h_) {                                                   \
      const int k_ = k0_ + h_ * 4;                                                     \
      float4 va_;                                                                      \
      if (k_ < KxPad) va_ = *reinterpret_cast<const float4*>(Ax + (size_t)mG * axStride + k_); \
      else            va_ = *reinterpret_cast<const float4*>(Ah + (size_t)mG * HID + (k_ - KxPad)); \
      fa[h_*4+0] = va_.x; fa[h_*4+1] = va_.y; fa[h_*4+2] = va_.z; fa[h_*4+3] = va_.w;  \
      float4 vb_;                                                                      \
      if (k_ >= KxPad) {                                                               \
        vb_ = *reinterpret_cast<const float4*>(Whh + origRow * HID + (k_ - KxPad));    \
      } else if (k_ + 3 < Kx) {                                                        \
        vb_ = *reinterpret_cast<const float4*>(Wih + origRow * Kx + k_);               \
      } else if (k_ >= Kx) {                                                           \
        vb_ = make_float4(0.f, 0.f, 0.f, 0.f);                                         \
      } else {                                                                         \
        vb_.x = (k_+0 < Kx) ? Wih[origRow * Kx + k_+0] : 0.f;                          \
        vb_.y = (k_+1 < Kx) ? Wih[origRow * Kx + k_+1] : 0.f;                          \
        vb_.z = (k_+2 < Kx) ? Wih[origRow * Kx + k_+2] : 0.f;                          \
        vb_.w = (k_+3 < Kx) ? Wih[origRow * Kx + k_+3] : 0.f;                          \
      }                                                                                \
      fb[h_*4+0] = vb_.x; fb[h_*4+1] = vb_.y; fb[h_*4+2] = vb_.z; fb[h_*4+3] = vb_.w;  \
    }                                                                                  \
  } while (0)

#define STORE_SPLIT(arrH, arrL, src, off)                                              \
  do {                                                                                 \
    float h0_ = rn_tf32(src[off+0]), h1_ = rn_tf32(src[off+1]);                        \
    float h2_ = rn_tf32(src[off+2]), h3_ = rn_tf32(src[off+3]);                        \
    *reinterpret_cast<float4*>(&arrH[rowLd][kb + off]) = make_float4(h0_, h1_, h2_, h3_); \
    *reinterpret_cast<float4*>(&arrL[rowLd][kb + off]) = make_float4(                  \
        rn_tf32(src[off+0] - h0_), rn_tf32(src[off+1] - h1_),                          \
        rn_tf32(src[off+2] - h2_), rn_tf32(src[off+3] - h3_));                         \
  } while (0)

  float acc[2][4][4];
#pragma unroll
  for (int a = 0; a < 2; ++a)
#pragma unroll
    for (int b = 0; b < 4; ++b)
#pragma unroll
      for (int c = 0; c < 4; ++c) acc[a][b][c] = 0.f;

  LOAD_CHUNK(0);

  for (int it = 0; it < iters; ++it) {
    __syncthreads();
    STORE_SPLIT(AsH, AsL, fa, 0);
    STORE_SPLIT(AsH, AsL, fa, 4);
    STORE_SPLIT(BsH, BsL, fb, 0);
    STORE_SPLIT(BsH, BsL, fb, 4);
    __syncthreads();
    if (it + 1 < iters) LOAD_CHUNK(it + 1);

#pragma unroll
    for (int k8 = 0; k8 < 2; ++k8) {
      const int kk = k8 * 8 + q;
      uint32_t aH[2][4], aL[2][4], bH[4][2], bL[4][2];
#pragma unroll
      for (int mt = 0; mt < 2; ++mt) {
        const int r = wm * 32 + mt * 16 + gid;
        aH[mt][0] = __float_as_uint(AsH[r][kk]);
        aH[mt][1] = __float_as_uint(AsH[r + 8][kk]);
        aH[mt][2] = __float_as_uint(AsH[r][kk + 4]);
        aH[mt][3] = __float_as_uint(AsH[r + 8][kk + 4]);
        aL[mt][0] = __float_as_uint(AsL[r][kk]);
        aL[mt][1] = __float_as_uint(AsL[r + 8][kk]);
        aL[mt][2] = __float_as_uint(AsL[r][kk + 4]);
        aL[mt][3] = __float_as_uint(AsL[r + 8][kk + 4]);
      }
#pragma unroll
      for (int nt = 0; nt < 4; ++nt) {
        const int nn = wn * 32 + nt * 8 + gid;
        bH[nt][0] = __float_as_uint(BsH[nn][kk]);
        bH[nt][1] = __float_as_uint(BsH[nn][kk + 4]);
        bL[nt][0] = __float_as_uint(BsL[nn][kk]);
        bL[nt][1] = __float_as_uint(BsL[nn][kk + 4]);
      }
#pragma unroll
      for (int mt = 0; mt < 2; ++mt)
#pragma unroll
        for (int nt = 0; nt < 4; ++nt) {
          mma_tf32(acc[mt][nt], aL[mt], bH[nt]);
          mma_tf32(acc[mt][nt], aH[mt], bL[nt]);
          mma_tf32(acc[mt][nt], aH[mt], bH[nt]);
        }
    }
  }

  // ---------------- epilogue: bias + activations + c/h update -------------------
  // C frag: c0:(row gid, col 2q) c1:(row gid, col 2q+1) c2/c3: row gid+8.
  // Even-q threads hold (i,f) pre-acts, odd-q neighbors hold (g,o) of same unit.
  const int cWarp = nBase + wn * 32;
  const int mWarp = mBase + wm * 32;
#pragma unroll
  for (int mt = 0; mt < 2; ++mt) {
#pragma unroll
    for (int nt = 0; nt < 4; ++nt) {
      const float p0 = __shfl_xor_sync(0xffffffffu, acc[mt][nt][0], 1);
      const float p1 = __shfl_xor_sync(0xffffffffu, acc[mt][nt][1], 1);
      const float p2 = __shfl_xor_sync(0xffffffffu, acc[mt][nt][2], 1);
      const float p3 = __shfl_xor_sync(0xffffffffu, acc[mt][nt][3], 1);
      if ((lane & 1) == 0) {
        const int cg = cWarp + nt * 8 + 2 * q;   // multiple of 4
        const int j  = cg >> 2;                  // hidden unit
        const float bi = bias[j];
        const float bf = bias[HID + j];
        const float bg = bias[2 * HID + j];
        const float bo = bias[3 * HID + j];
        const int r0 = mWarp + mt * 16 + gid;
        {
          const float ig = sigmoidf_(acc[mt][nt][0] + bi);
          const float fg = sigmoidf_(acc[mt][nt][1] + bf);
          const float gg = tanhf(p0 + bg);
          const float og = sigmoidf_(p1 + bo);
          const float cold = cState[(size_t)r0 * HID + j];
          const float cn = fg * cold + ig * gg;
          cState[(size_t)r0 * HID + j] = cn;
          hOut[(size_t)r0 * HID + j]   = og * tanhf(cn);
        }
        {
          const int r1 = r0 + 8;
          const float ig = sigmoidf_(acc[mt][nt][2] + bi);
          const float fg = sigmoidf_(acc[mt][nt][3] + bf);
          const float gg = tanhf(p2 + bg);
          const float og = sigmoidf_(p3 + bo);
          const float cold = cState[(size_t)r1 * HID + j];
          const float cn = fg * cold + ig * gg;
          cState[(size_t)r1 * HID + j] = cn;
          hOut[(size_t)r1 * HID + j]   = og * tanhf(cn);
        }
      }
    }
  }
#undef LOAD_CHUNK
#undef STORE_SPLIT
}

// ---------------- init / staging -------------------------------------------------
__global__ void init_zero_kernel() {
  const int i = blockIdx.x * blockDim.x + threadIdx.x;
  if (i < NB * HID) {
    g_c0[i] = 0.f;
    g_c1[i] = 0.f;
    g_zero[i] = 0.f;
  }
}

__global__ void stage_x_kernel(const float* __restrict__ x) {
  const int i = blockIdx.x * blockDim.x + threadIdx.x;
  if (i < TSTEPS * NB * 16) {
    const int k = i & 15;
    const int m = (i >> 4) & (NB - 1);
    const int t = i >> 11;
    g_xpad[i] = (k < 8) ? x[((size_t)m * TSTEPS + t) * 8 + k] : 0.f;
  }
  if (i < NB * 16) {
    const int m = i >> 4;
    const int k = i & 15;
    g_predpad[i] = (k == 0) ? x[((size_t)m * TSTEPS + (TSTEPS - 1)) * 8] : 0.f;
  }
}

// ---------------- projection: pred = h1 @ projW^T + b ----------------------------
__global__ void proj_kernel(const float* __restrict__ h, const float* __restrict__ W,
                            const float* __restrict__ pb, float* __restrict__ out, int t) {
  const int warp = blockIdx.x * (blockDim.x >> 5) + (threadIdx.x >> 5);  // batch row
  const int lane = threadIdx.x & 31;
  const float* hr = h + (size_t)warp * HID;
  float s = 0.f;
  for (int k = lane; k < HID; k += 32) s += hr[k] * W[k];
#pragma unroll
  for (int o = 16; o; o >>= 1) s += __shfl_xor_sync(0xffffffffu, s, o);
  if (lane == 0) {
    const float p = s + pb[0];
    out[warp * HORIZON + t] = p;   // output (B, HORIZON)
    g_predpad[warp * 16] = p;      // feeds next decoder step
  }
}

// ---------------- host side ------------------------------------------------------
extern "C" void kernel_launch(void* const* d_in, const int* in_sizes, int n_in,
                              void* d_out, int out_size) {
  const float* x     = (const float*)d_in[0];
  const float* eWih0 = (const float*)d_in[1];
  const float* eWhh0 = (const float*)d_in[2];
  const float* eb0   = (const float*)d_in[3];
  const float* eWih1 = (const float*)d_in[4];
  const float* eWhh1 = (const float*)d_in[5];
  const float* eb1   = (const float*)d_in[6];
  const float* dWih0 = (const float*)d_in[7];
  const float* dWhh0 = (const float*)d_in[8];
  const float* db0   = (const float*)d_in[9];
  const float* dWih1 = (const float*)d_in[10];
  const float* dWhh1 = (const float*)d_in[11];
  const float* db1   = (const float*)d_in[12];
  const float* projW = (const float*)d_in[13];
  const float* projb = (const float*)d_in[14];
  float* out = (float*)d_out;

  float *ys0, *hB, *hd0, *hd1, *c0, *c1, *z, *xpad, *predpad;
  cudaGetSymbolAddress((void**)&ys0, g_ys0);
  cudaGetSymbolAddress((void**)&hB, g_hB);
  cudaGetSymbolAddress((void**)&hd0, g_hd0);
  cudaGetSymbolAddress((void**)&hd1, g_hd1);
  cudaGetSymbolAddress((void**)&c0, g_c0);
  cudaGetSymbolAddress((void**)&c1, g_c1);
  cudaGetSymbolAddress((void**)&z, g_zero);
  cudaGetSymbolAddress((void**)&xpad, g_xpad);
  cudaGetSymbolAddress((void**)&predpad, g_predpad);

  init_zero_kernel<<<(NB * HID + 255) / 256, 256>>>();
  stage_x_kernel<<<(TSTEPS * NB * 16 + 255) / 256, 256>>>(x);

  const dim3 grid(64, 2);
  const dim3 blk(128);
  const size_t HS = (size_t)NB * HID;

  // encoder layer 0
  for (int t = 0; t < TSTEPS; ++t) {
    const float* ah = (t == 0) ? z : (ys0 + (size_t)(t - 1) * HS);
    lstm_step_kernel<<<grid, blk>>>(xpad + (size_t)t * NB * 16, 16, 8, 16, ah,
                                    eWih0, eWhh0, eb0, c0, ys0 + (size_t)t * HS);
  }
  // encoder layer 1
  for (int t = 0; t < TSTEPS; ++t) {
    const float* ah = (t == 0) ? z : (hB + (size_t)((t - 1) & 1) * HS);
    lstm_step_kernel<<<grid, blk>>>(ys0 + (size_t)t * HS, HID, HID, HID, ah,
                                    eWih1, eWhh1, eb1, c1, hB + (size_t)(t & 1) * HS);
  }
  // decoder
  for (int t = 0; t < HORIZON; ++t) {
    const float* ah0 = (t == 0) ? (ys0 + (size_t)(TSTEPS - 1) * HS)
                                : (hd0 + (size_t)((t - 1) & 1) * HS);
    lstm_step_kernel<<<grid, blk>>>(predpad, 16, 1, 16, ah0,
                                    dWih0, dWhh0, db0, c0, hd0 + (size_t)(t & 1) * HS);
    const float* ah1 = (t == 0) ? (hB + HS)
                                : (hd1 + (size_t)((t - 1) & 1) * HS);
    lstm_step_kernel<<<grid, blk>>>(hd0 + (size_t)(t & 1) * HS, HID, HID, HID, ah1,
                                    dWih1, dWhh1, db1, c1, hd1 + (size_t)(t & 1) * HS);
    proj_kernel<<<16, 256>>>(hd1 + (size_t)(t & 1) * HS, projW, projb, out, t);
  }
}

// round 4
// speedup vs baseline: 1.4733x; 1.4733x over previous
#include <cuda_runtime.h>
#include <cstdint>
#include <cstddef>

#define HID 1024
#define NB 128        // batch
#define TSTEPS 256
#define HORIZON 24
#define NCTA 128      // persistent grid size (<=148 SMs -> co-resident, grid barrier safe)

// ---------------- persistent scratch (__device__ globals; no allocs) -------------
__device__ float g_ys0[(size_t)TSTEPS * NB * HID];   // encoder layer0 outputs
__device__ float g_hB[2 * NB * HID];                 // enc layer1 h ping-pong
__device__ float g_hd0[2 * NB * HID];                // dec layer0 h ping-pong
__device__ float g_hd1[2 * NB * HID];                // dec layer1 h ping-pong
__device__ float g_c0[NB * HID];
__device__ float g_c1[NB * HID];
__device__ float g_zero[NB * HID];
__device__ float g_xpad[TSTEPS * NB * 16];           // x staged 16-wide, zero padded
__device__ float g_predpad[NB * 16];                 // decoder scalar input, padded
__device__ unsigned g_bar_cnt;
__device__ volatile unsigned g_bar_epoch;

// ---------------- helpers --------------------------------------------------------
__device__ __forceinline__ float rn_tf32(float x) {
  uint32_t r;
  asm("cvt.rna.tf32.f32 %0, %1;" : "=r"(r) : "f"(x));
  return __uint_as_float(r);
}

__device__ __forceinline__ void mma_tf32(float d[4], const uint32_t a[4], const uint32_t b[2]) {
  asm volatile(
      "mma.sync.aligned.m16n8k8.row.col.f32.tf32.tf32.f32 "
      "{%0,%1,%2,%3}, {%4,%5,%6,%7}, {%8,%9}, {%0,%1,%2,%3};\n"
      : "+f"(d[0]), "+f"(d[1]), "+f"(d[2]), "+f"(d[3])
      : "r"(a[0]), "r"(a[1]), "r"(a[2]), "r"(a[3]), "r"(b[0]), "r"(b[1]));
}

__device__ __forceinline__ float sigmoidf_(float x) { return 1.f / (1.f + expf(-x)); }

// ---------------- persistent mega-kernel -----------------------------------------
// Tile ownership fixed: CTA bx -> (mBase = (bx>>6)*64, nBase = (bx&63)*64).
// 8 warps: wm = wid>>2 (M), wn = (wid>>1)&1 (N), wk = wid&1 (K-split half).
// Warp tile 32x32, 3xTF32 (hi/lo split), split-K reduced via smem per step.
__global__ void __launch_bounds__(256, 1) lstm_persist(
    const float* __restrict__ eWih0, const float* __restrict__ eWhh0, const float* __restrict__ eb0,
    const float* __restrict__ eWih1, const float* __restrict__ eWhh1, const float* __restrict__ eb1,
    const float* __restrict__ dWih0, const float* __restrict__ dWhh0, const float* __restrict__ db0,
    const float* __restrict__ dWih1, const float* __restrict__ dWhh1, const float* __restrict__ db1,
    const float* __restrict__ projW, const float* __restrict__ projb,
    float* __restrict__ out)
{
  __shared__ __align__(16) float sAH[2][64][20];
  __shared__ __align__(16) float sAL[2][64][20];
  __shared__ __align__(16) float sBH[2][64][20];
  __shared__ __align__(16) float sBL[2][64][20];

  const int tid  = threadIdx.x;
  const int lane = tid & 31;
  const int wid  = tid >> 5;
  const int wk   = wid & 1;
  const int wn   = (wid >> 1) & 1;
  const int wm   = wid >> 2;
  const int gid  = lane >> 2;
  const int q    = lane & 3;
  const int bx   = blockIdx.x;
  const int mBase = (bx >> 6) * 64;
  const int nBase = (bx & 63) * 64;

  // global-load mapping: 256 threads, each 1 A-float4 + 1 B-float4 per k-chunk(16)
  const int aRow = tid >> 2;            // 0..63
  const int kq   = (tid & 3) << 2;      // 0,4,8,12
  const int mG = mBase + aRow;
  const int nG = nBase + aRow;
  const size_t origRow = (size_t)(nG & 3) * HID + (nG >> 2);  // gate-interleave row

  unsigned barNo = 0;
  float* red = &sAH[0][0][0];           // reduction / proj scratch (reused)

  auto grid_barrier = [&]() {
    ++barNo;
    __threadfence();
    __syncthreads();
    if (tid == 0) {
      unsigned old = atomicAdd(&g_bar_cnt, 1u);
      if (old == NCTA - 1) {
        g_bar_cnt = 0;
        __threadfence();
        g_bar_epoch = barNo;            // release
      } else {
        while (g_bar_epoch < barNo) __nanosleep(32);
      }
    }
    __syncthreads();
    __threadfence();                    // acquire: invalidate L1, see peers' h writes
  };

  auto step = [&](const float* Ax, int axStride, int Kx, int KxPad,
                  const float* Ah, const float* Wih, const float* Whh,
                  const float* bias, float* cS, float* hO) {
    const int iters = (KxPad + HID) >> 4;
    float4 ga, gb;

    auto LOADG = [&](int it) {
      const int k = it * 16 + kq;
      if (k < KxPad) ga = *reinterpret_cast<const float4*>(Ax + (size_t)mG * axStride + k);
      else           ga = *reinterpret_cast<const float4*>(Ah + (size_t)mG * HID + (k - KxPad));
      if (k >= KxPad) {
        gb = *reinterpret_cast<const float4*>(Whh + origRow * HID + (k - KxPad));
      } else if (k + 3 < Kx) {
        gb = *reinterpret_cast<const float4*>(Wih + origRow * Kx + k);
      } else if (k >= Kx) {
        gb = make_float4(0.f, 0.f, 0.f, 0.f);
      } else {
        gb.x = (k + 0 < Kx) ? Wih[origRow * Kx + k + 0] : 0.f;
        gb.y = (k + 1 < Kx) ? Wih[origRow * Kx + k + 1] : 0.f;
        gb.z = (k + 2 < Kx) ? Wih[origRow * Kx + k + 2] : 0.f;
        gb.w = (k + 3 < Kx) ? Wih[origRow * Kx + k + 3] : 0.f;
      }
    };
    auto STORE = [&](int p) {
      float h0 = rn_tf32(ga.x), h1 = rn_tf32(ga.y), h2 = rn_tf32(ga.z), h3 = rn_tf32(ga.w);
      *reinterpret_cast<float4*>(&sAH[p][aRow][kq]) = make_float4(h0, h1, h2, h3);
      *reinterpret_cast<float4*>(&sAL[p][aRow][kq]) =
          make_float4(rn_tf32(ga.x - h0), rn_tf32(ga.y - h1), rn_tf32(ga.z - h2), rn_tf32(ga.w - h3));
      h0 = rn_tf32(gb.x); h1 = rn_tf32(gb.y); h2 = rn_tf32(gb.z); h3 = rn_tf32(gb.w);
      *reinterpret_cast<float4*>(&sBH[p][aRow][kq]) = make_float4(h0, h1, h2, h3);
      *reinterpret_cast<float4*>(&sBL[p][aRow][kq]) =
          make_float4(rn_tf32(gb.x - h0), rn_tf32(gb.y - h1), rn_tf32(gb.z - h2), rn_tf32(gb.w - h3));
    };

    float acc[2][4][4];
#pragma unroll
    for (int a = 0; a < 2; ++a)
#pragma unroll
      for (int b = 0; b < 4; ++b)
#pragma unroll
        for (int c = 0; c < 4; ++c) acc[a][b][c] = 0.f;

    LOADG(0); STORE(0);
    LOADG(1);
    __syncthreads();

    const int kk = wk * 8 + q;          // this warp's K-split half within the chunk
    for (int it = 0; it < iters; ++it) {
      const int p = it & 1;
      uint32_t aH[2][4], aL[2][4], bH[4][2], bL[4][2];
#pragma unroll
      for (int mt = 0; mt < 2; ++mt) {
        const int r = wm * 32 + mt * 16 + gid;
        aH[mt][0] = __float_as_uint(sAH[p][r][kk]);
        aH[mt][1] = __float_as_uint(sAH[p][r + 8][kk]);
        aH[mt][2] = __float_as_uint(sAH[p][r][kk + 4]);
        aH[mt][3] = __float_as_uint(sAH[p][r + 8][kk + 4]);
        aL[mt][0] = __float_as_uint(sAL[p][r][kk]);
        aL[mt][1] = __float_as_uint(sAL[p][r + 8][kk]);
        aL[mt][2] = __float_as_uint(sAL[p][r][kk + 4]);
        aL[mt][3] = __float_as_uint(sAL[p][r + 8][kk + 4]);
      }
#pragma unroll
      for (int nt = 0; nt < 4; ++nt) {
        const int nn = wn * 32 + nt * 8 + gid;
        bH[nt][0] = __float_as_uint(sBH[p][nn][kk]);
        bH[nt][1] = __float_as_uint(sBH[p][nn][kk + 4]);
        bL[nt][0] = __float_as_uint(sBL[p][nn][kk]);
        bL[nt][1] = __float_as_uint(sBL[p][nn][kk + 4]);
      }
      if (it + 1 < iters) STORE(p ^ 1);         // stage data for it+1
      if (it + 2 < iters) LOADG(it + 2);        // prefetch globals for it+2
#pragma unroll
      for (int mt = 0; mt < 2; ++mt)
#pragma unroll
        for (int nt = 0; nt < 4; ++nt) {
          mma_tf32(acc[mt][nt], aL[mt], bH[nt]);
          mma_tf32(acc[mt][nt], aH[mt], bL[nt]);
          mma_tf32(acc[mt][nt], aH[mt], bH[nt]);
        }
      __syncthreads();
    }

    // ---- split-K reduction: wk==1 warps hand their accs to wk==0 partners ----
    float* af = &acc[0][0][0];
    const int slot = (((wid >> 1) * 32) + lane) * 32;
    if (wk) {
#pragma unroll
      for (int i = 0; i < 32; ++i) red[slot + i] = af[i];
    }
    __syncthreads();
    if (!wk) {
#pragma unroll
      for (int i = 0; i < 32; ++i) af[i] += red[slot + i];

      // ---- epilogue: bias + activations + c/h update (wk==0 warps: full tile) ----
      const int cWarp = nBase + wn * 32;
      const int mWarp = mBase + wm * 32;
#pragma unroll
      for (int mt = 0; mt < 2; ++mt) {
#pragma unroll
        for (int nt = 0; nt < 4; ++nt) {
          const float p0 = __shfl_xor_sync(0xffffffffu, acc[mt][nt][0], 1);
          const float p1 = __shfl_xor_sync(0xffffffffu, acc[mt][nt][1], 1);
          const float p2 = __shfl_xor_sync(0xffffffffu, acc[mt][nt][2], 1);
          const float p3 = __shfl_xor_sync(0xffffffffu, acc[mt][nt][3], 1);
          if ((lane & 1) == 0) {
            const int cg = cWarp + nt * 8 + 2 * q;
            const int j  = cg >> 2;
            const float bi = bias[j];
            const float bf = bias[HID + j];
            const float bg = bias[2 * HID + j];
            const float bo = bias[3 * HID + j];
            const int r0 = mWarp + mt * 16 + gid;
            {
              const float ig = sigmoidf_(acc[mt][nt][0] + bi);
              const float fg = sigmoidf_(acc[mt][nt][1] + bf);
              const float gg = tanhf(p0 + bg);
              const float og = sigmoidf_(p1 + bo);
              const float cold = cS[(size_t)r0 * HID + j];
              const float cn = fg * cold + ig * gg;
              cS[(size_t)r0 * HID + j] = cn;
              hO[(size_t)r0 * HID + j] = og * tanhf(cn);
            }
            {
              const int r1 = r0 + 8;
              const float ig = sigmoidf_(acc[mt][nt][2] + bi);
              const float fg = sigmoidf_(acc[mt][nt][3] + bf);
              const float gg = tanhf(p2 + bg);
              const float og = sigmoidf_(p3 + bo);
              const float cold = cS[(size_t)r1 * HID + j];
              const float cn = fg * cold + ig * gg;
              cS[(size_t)r1 * HID + j] = cn;
              hO[(size_t)r1 * HID + j] = og * tanhf(cn);
            }
          }
        }
      }
    }
  };

  const size_t HS = (size_t)NB * HID;

  // -------- encoder layer 0 --------
  for (int t = 0; t < TSTEPS; ++t) {
    const float* ah = t ? (g_ys0 + (size_t)(t - 1) * HS) : g_zero;
    step(g_xpad + (size_t)t * NB * 16, 16, 8, 16, ah, eWih0, eWhh0, eb0, g_c0,
         g_ys0 + (size_t)t * HS);
    grid_barrier();
  }
  // -------- encoder layer 1 --------
  for (int t = 0; t < TSTEPS; ++t) {
    const float* ah = t ? (g_hB + (size_t)((t - 1) & 1) * HS) : g_zero;
    step(g_ys0 + (size_t)t * HS, HID, HID, HID, ah, eWih1, eWhh1, eb1, g_c1,
         g_hB + (size_t)(t & 1) * HS);
    grid_barrier();
  }
  // -------- decoder --------
  for (int t = 0; t < HORIZON; ++t) {
    const float* ah0 = t ? (g_hd0 + (size_t)((t - 1) & 1) * HS)
                         : (g_ys0 + (size_t)(TSTEPS - 1) * HS);
    step(g_predpad, 16, 1, 16, ah0, dWih0, dWhh0, db0, g_c0, g_hd0 + (size_t)(t & 1) * HS);
    grid_barrier();
    const float* ah1 = t ? (g_hd1 + (size_t)((t - 1) & 1) * HS) : (g_hB + HS);
    step(g_hd0 + (size_t)(t & 1) * HS, HID, HID, HID, ah1, dWih1, dWhh1, db1, g_c1,
         g_hd1 + (size_t)(t & 1) * HS);
    grid_barrier();
    // projection: CTA b handles batch row b
    {
      const float* hr = g_hd1 + (size_t)(t & 1) * HS + (size_t)bx * HID;
      float s = 0.f;
      for (int k = tid; k < HID; k += 256) s += hr[k] * projW[k];
#pragma unroll
      for (int o = 16; o; o >>= 1) s += __shfl_xor_sync(0xffffffffu, s, o);
      if (lane == 0) red[wid] = s;
      __syncthreads();
      if (tid == 0) {
        float tot = 0.f;
#pragma unroll
        for (int i = 0; i < 8; ++i) tot += red[i];
        const float p = tot + projb[0];
        out[bx * HORIZON + t] = p;
        g_predpad[bx * 16] = p;
      }
    }
    grid_barrier();
  }
}

// ---------------- init / staging -------------------------------------------------
__global__ void init_kernel(const float* __restrict__ x) {
  const int i = blockIdx.x * blockDim.x + threadIdx.x;
  if (i == 0) { g_bar_cnt = 0; g_bar_epoch = 0; }
  if (i < NB * HID) {
    g_c0[i] = 0.f;
    g_c1[i] = 0.f;
    g_zero[i] = 0.f;
  }
  if (i < TSTEPS * NB * 16) {
    const int k = i & 15;
    const int m = (i >> 4) & (NB - 1);
    const int t = i >> 11;
    g_xpad[i] = (k < 8) ? x[((size_t)m * TSTEPS + t) * 8 + k] : 0.f;
  }
  if (i < NB * 16) {
    const int m = i >> 4;
    const int k = i & 15;
    g_predpad[i] = (k == 0) ? x[((size_t)m * TSTEPS + (TSTEPS - 1)) * 8] : 0.f;
  }
}

// ---------------- host side ------------------------------------------------------
extern "C" void kernel_launch(void* const* d_in, const int* in_sizes, int n_in,
                              void* d_out, int out_size) {
  const float* x     = (const float*)d_in[0];
  const float* eWih0 = (const float*)d_in[1];
  const float* eWhh0 = (const float*)d_in[2];
  const float* eb0   = (const float*)d_in[3];
  const float* eWih1 = (const float*)d_in[4];
  const float* eWhh1 = (const float*)d_in[5];
  const float* eb1   = (const float*)d_in[6];
  const float* dWih0 = (const float*)d_in[7];
  const float* dWhh0 = (const float*)d_in[8];
  const float* db0   = (const float*)d_in[9];
  const float* dWih1 = (const float*)d_in[10];
  const float* dWhh1 = (const float*)d_in[11];
  const float* db1   = (const float*)d_in[12];
  const float* projW = (const float*)d_in[13];
  const float* projb = (const float*)d_in[14];
  float* out = (float*)d_out;

  init_kernel<<<(TSTEPS * NB * 16 + 255) / 256, 256>>>(x);
  lstm_persist<<<NCTA, 256>>>(eWih0, eWhh0, eb0, eWih1, eWhh1, eb1,
                              dWih0, dWhh0, db0, dWih1, dWhh1, db1,
                              projW, projb, out);
}

// round 6
// speedup vs baseline: 2.2689x; 1.5400x over previous
#include <cuda_runtime.h>
#include <cuda_bf16.h>
#include <cstdint>
#include <cstddef>

#define HID 1024
#define NB 128
#define TSTEPS 256
#define HORIZON 24
#define NCTA 128
#define HP 512                 // pairs per h row (1024 k / 2)
#define XP 16                  // pairs per x row (32 k, zero padded)
#define P0 (XP + HP)           // 528 pairs: enc0/dec0 total K pairs
#define P1 (2 * HP)            // 1024 pairs: enc1/dec1 total K pairs

// ---------------- persistent scratch (__device__ globals; no allocs) -------------
// weights pre-split to (hi bf16x2, lo bf16x2) pairs, gate-interleaved row order
__device__ uint2 g_We0[(size_t)4096 * P0];
__device__ uint2 g_We1[(size_t)4096 * P1];
__device__ uint2 g_Wd0[(size_t)4096 * P0];
__device__ uint2 g_Wd1[(size_t)4096 * P1];
// activations stored as split pairs
__device__ uint2 g_ys0p[(size_t)TSTEPS * NB * HP];   // enc layer0 outputs
__device__ uint2 g_hBp[2 * NB * HP];
__device__ uint2 g_hd0p[2 * NB * HP];
__device__ uint2 g_hd1p[2 * NB * HP];
__device__ uint2 g_zerop[NB * HP];
__device__ uint2 g_xp[(size_t)TSTEPS * NB * XP];
__device__ uint2 g_predp[NB * XP];
__device__ float g_c0[NB * HID];
__device__ float g_c1[NB * HID];
__device__ unsigned g_bar_cnt;
__device__ volatile unsigned g_bar_epoch;

// ---------------- helpers --------------------------------------------------------
__device__ __forceinline__ uint32_t bf2pack(float hi, float lo) {
  uint32_t r;
  asm("cvt.rn.bf16x2.f32 %0, %1, %2;" : "=r"(r) : "f"(hi), "f"(lo));
  return r;
}
// split (v0 -> low half, v1 -> high half) into hi-plane + lo-plane bf16x2
__device__ __forceinline__ uint2 split2(float v0, float v1) {
  uint32_t hp = bf2pack(v1, v0);
  float h0 = __uint_as_float(hp << 16);
  float h1 = __uint_as_float(hp & 0xFFFF0000u);
  uint32_t lp = bf2pack(v1 - h1, v0 - h0);
  return make_uint2(hp, lp);
}

__device__ __forceinline__ void mma_bf16(float d[4], const uint32_t a[4], const uint32_t b[2]) {
  asm volatile(
      "mma.sync.aligned.m16n8k16.row.col.f32.bf16.bf16.f32 "
      "{%0,%1,%2,%3}, {%4,%5,%6,%7}, {%8,%9}, {%0,%1,%2,%3};\n"
      : "+f"(d[0]), "+f"(d[1]), "+f"(d[2]), "+f"(d[3])
      : "r"(a[0]), "r"(a[1]), "r"(a[2]), "r"(a[3]), "r"(b[0]), "r"(b[1]));
}

__device__ __forceinline__ float sigmoidf_(float x) { return 1.f / (1.f + expf(-x)); }

// ---------------- persistent mega-kernel -----------------------------------------
// CTA bx: mBase=(bx>>6)*64, nBase=(bx&63)*64. 8 warps: wm=wid>>2, wn=(wid>>1)&1,
// wk=wid&1. Warp tile 32x32. Super-iteration = 2 chunks of K=16; group wk computes
// chunk 2s+wk. smem: [stage2][slot2][64 rows][12 uint2] for A and B (48KB static).
__global__ void __launch_bounds__(256, 1) lstm_persist(
    const float* __restrict__ eb0, const float* __restrict__ eb1,
    const float* __restrict__ db0, const float* __restrict__ db1,
    const float* __restrict__ projW, const float* __restrict__ projb,
    float* __restrict__ out)
{
  __shared__ __align__(16) uint2 sA[4 * 64 * 12];   // 24576 B
  __shared__ __align__(16) uint2 sB[4 * 64 * 12];   // 24576 B
  float* red = reinterpret_cast<float*>(sA);        // overlay (post-pipeline use only)

  const int tid  = threadIdx.x;
  const int lane = tid & 31;
  const int wid  = tid >> 5;
  const int wk   = wid & 1;
  const int wn   = (wid >> 1) & 1;
  const int wm   = wid >> 2;
  const int gid  = lane >> 2;
  const int q    = lane & 3;
  const int bx   = blockIdx.x;
  const int mBase = (bx >> 6) * 64;
  const int nBase = (bx & 63) * 64;

  const int sRow = tid >> 2;            // staging row 0..63
  const int pq   = (tid & 3) * 2;       // pair offset within chunk (0,2,4,6)
  const int mG = mBase + sRow;
  const int nG = nBase + sRow;

  unsigned barNo = 0;
  auto grid_barrier = [&]() {
    ++barNo;
    __threadfence();
    __syncthreads();
    if (tid == 0) {
      unsigned old = atomicAdd(&g_bar_cnt, 1u);
      if (old == NCTA - 1) {
        g_bar_cnt = 0;
        __threadfence();
        g_bar_epoch = barNo;
      } else {
        while (g_bar_epoch < barNo) __nanosleep(32);
      }
    }
    __syncthreads();
    __threadfence();
  };

  auto step = [&](const uint2* __restrict__ Apx, int pxPairs,
                  const uint2* __restrict__ Ahp,
                  const uint2* __restrict__ gW, int P,
                  const float* __restrict__ bias,
                  float* __restrict__ cS, uint2* __restrict__ hOutP) {
    const int S = (P >> 3) >> 1;        // chunks = P/8 pairs-per-chunk; supers = /2

    uint4 pa[2], pbv[2];
    auto LOADG = [&](int c0) {
#pragma unroll
      for (int u = 0; u < 2; ++u) {
        const int pb = (c0 + u) * 8 + pq;
        const uint2* asrc = (pb < pxPairs)
            ? (Apx + (size_t)mG * pxPairs + pb)
            : (Ahp + (size_t)mG * HP + (pb - pxPairs));
        pa[u]  = *reinterpret_cast<const uint4*>(asrc);
        pbv[u] = *reinterpret_cast<const uint4*>(gW + (size_t)nG * P + pb);
      }
    };
    auto STORE = [&](int st) {
#pragma unroll
      for (int u = 0; u < 2; ++u) {
        *reinterpret_cast<uint4*>(&sA[((st * 2 + u) * 64 + sRow) * 12 + pq]) = pa[u];
        *reinterpret_cast<uint4*>(&sB[((st * 2 + u) * 64 + sRow) * 12 + pq]) = pbv[u];
      }
    };

    float acc[2][4][4];
#pragma unroll
    for (int a = 0; a < 2; ++a)
#pragma unroll
      for (int b = 0; b < 4; ++b)
#pragma unroll
        for (int c = 0; c < 4; ++c) acc[a][b][c] = 0.f;

    LOADG(0);
    STORE(0);
    LOADG(2);
    __syncthreads();

    for (int s = 0; s < S; ++s) {
      const int p = s & 1;
      const uint2* As = sA + (p * 2 + wk) * 64 * 12;
      const uint2* Bs = sB + (p * 2 + wk) * 64 * 12;
      uint32_t aH[2][4], aL[2][4], bH[4][2], bL[4][2];
#pragma unroll
      for (int mt = 0; mt < 2; ++mt) {
        const int r = wm * 32 + mt * 16 + gid;
        const uint2 u0 = As[r * 12 + q];
        const uint2 u1 = As[(r + 8) * 12 + q];
        const uint2 u2 = As[r * 12 + q + 4];
        const uint2 u3 = As[(r + 8) * 12 + q + 4];
        aH[mt][0] = u0.x; aH[mt][1] = u1.x; aH[mt][2] = u2.x; aH[mt][3] = u3.x;
        aL[mt][0] = u0.y; aL[mt][1] = u1.y; aL[mt][2] = u2.y; aL[mt][3] = u3.y;
      }
#pragma unroll
      for (int nt = 0; nt < 4; ++nt) {
        const int n = wn * 32 + nt * 8 + gid;
        const uint2 v0 = Bs[n * 12 + q];
        const uint2 v1 = Bs[n * 12 + q + 4];
        bH[nt][0] = v0.x; bH[nt][1] = v1.x;
        bL[nt][0] = v0.y; bL[nt][1] = v1.y;
      }
      if (s + 1 < S) STORE(p ^ 1);
      if (s + 2 < S) LOADG((s + 2) * 2);
#pragma unroll
      for (int mt = 0; mt < 2; ++mt)
#pragma unroll
        for (int nt = 0; nt < 4; ++nt) {
          mma_bf16(acc[mt][nt], aL[mt], bH[nt]);
          mma_bf16(acc[mt][nt], aH[mt], bL[nt]);
          mma_bf16(acc[mt][nt], aH[mt], bH[nt]);
        }
      __syncthreads();
    }

    // ---- split-K reduction: wk==1 warps hand accs to wk==0 partners ----
    float* af = &acc[0][0][0];
    const int slot = (((wid >> 1) * 32) + lane) * 32;
    if (wk) {
#pragma unroll
      for (int i = 0; i < 32; ++i) red[slot + i] = af[i];
    }
    __syncthreads();
    if (!wk) {
#pragma unroll
      for (int i = 0; i < 32; ++i) af[i] += red[slot + i];

      // ---- epilogue: bias + activations + c update + paired-h store ----
      const int cWarp = nBase + wn * 32;
      const int mWarp = mBase + wm * 32;
#pragma unroll
      for (int mt = 0; mt < 2; ++mt) {
#pragma unroll
        for (int nt = 0; nt < 4; ++nt) {
          const float p0 = __shfl_xor_sync(0xffffffffu, acc[mt][nt][0], 1);
          const float p1 = __shfl_xor_sync(0xffffffffu, acc[mt][nt][1], 1);
          const float p2 = __shfl_xor_sync(0xffffffffu, acc[mt][nt][2], 1);
          const float p3 = __shfl_xor_sync(0xffffffffu, acc[mt][nt][3], 1);
          const int cg = cWarp + nt * 8 + 2 * q;
          const int j  = cg >> 2;                  // odd lanes: unused results
          const float bi = bias[j];
          const float bf = bias[HID + j];
          const float bg = bias[2 * HID + j];
          const float bo = bias[3 * HID + j];
          const int r0 = mWarp + mt * 16 + gid;
          const int r1 = r0 + 8;
          float hn0, hn1;
          {
            const float ig = sigmoidf_(acc[mt][nt][0] + bi);
            const float fg = sigmoidf_(acc[mt][nt][1] + bf);
            const float gg = tanhf(p0 + bg);
            const float og = sigmoidf_(p1 + bo);
            const float cn = fg * cS[r0 * HID + j] + ig * gg;
            if ((lane & 1) == 0) cS[r0 * HID + j] = cn;
            hn0 = og * tanhf(cn);
          }
          {
            const float ig = sigmoidf_(acc[mt][nt][2] + bi);
            const float fg = sigmoidf_(acc[mt][nt][3] + bf);
            const float gg = tanhf(p2 + bg);
            const float og = sigmoidf_(p3 + bo);
            const float cn = fg * cS[r1 * HID + j] + ig * gg;
            if ((lane & 1) == 0) cS[r1 * HID + j] = cn;
            hn1 = og * tanhf(cn);
          }
          // pair columns j (q=0 lane) with j+1 (q=2 lane) -> one uint2 store
          const float x0 = __shfl_xor_sync(0xffffffffu, hn0, 2);
          const float x1 = __shfl_xor_sync(0xffffffffu, hn1, 2);
          if (q == 0) {
            const int jp = (cWarp + nt * 8) >> 3;
            hOutP[(size_t)r0 * HP + jp] = split2(hn0, x0);
            hOutP[(size_t)r1 * HP + jp] = split2(hn1, x1);
          }
        }
      }
    }
  };

  const size_t HS = (size_t)NB * HP;

  // -------- encoder layer 0 --------
  for (int t = 0; t < TSTEPS; ++t) {
    const uint2* ah = t ? (g_ys0p + (size_t)(t - 1) * HS) : g_zerop;
    step(g_xp + (size_t)t * NB * XP, XP, ah, g_We0, P0, eb0, g_c0,
         g_ys0p + (size_t)t * HS);
    grid_barrier();
  }
  // -------- encoder layer 1 --------
  for (int t = 0; t < TSTEPS; ++t) {
    const uint2* ah = t ? (g_hBp + (size_t)((t - 1) & 1) * HS) : g_zerop;
    step(g_ys0p + (size_t)t * HS, HP, ah, g_We1, P1, eb1, g_c1,
         g_hBp + (size_t)(t & 1) * HS);
    grid_barrier();
  }
  // -------- decoder --------
  for (int t = 0; t < HORIZON; ++t) {
    const uint2* ah0 = t ? (g_hd0p + (size_t)((t - 1) & 1) * HS)
                         : (g_ys0p + (size_t)(TSTEPS - 1) * HS);
    step(g_predp, XP, ah0, g_Wd0, P0, db0, g_c0, g_hd0p + (size_t)(t & 1) * HS);
    grid_barrier();
    const uint2* ah1 = t ? (g_hd1p + (size_t)((t - 1) & 1) * HS) : (g_hBp + HS);
    step(g_hd0p + (size_t)(t & 1) * HS, HP, ah1, g_Wd1, P1, db1, g_c1,
         g_hd1p + (size_t)(t & 1) * HS);
    grid_barrier();
    // projection: CTA b handles batch row b (reconstruct h from pairs)
    {
      const uint2* hr = g_hd1p + (size_t)(t & 1) * HS + (size_t)bx * HP;
      float s = 0.f;
      for (int p = tid; p < HP; p += 256) {
        const uint2 u = hr[p];
        const float h0 = __uint_as_float(u.x << 16) + __uint_as_float(u.y << 16);
        const float h1 = __uint_as_float(u.x & 0xFFFF0000u) +
                         __uint_as_float(u.y & 0xFFFF0000u);
        s += h0 * projW[2 * p] + h1 * projW[2 * p + 1];
      }
#pragma unroll
      for (int o = 16; o; o >>= 1) s += __shfl_xor_sync(0xffffffffu, s, o);
      if (lane == 0) red[wid] = s;
      __syncthreads();
      if (tid == 0) {
        float tot = 0.f;
#pragma unroll
        for (int i = 0; i < 8; ++i) tot += red[i];
        const float p = tot + projb[0];
        out[bx * HORIZON + t] = p;
        g_predp[bx * XP] = split2(p, 0.f);
      }
      __syncthreads();
    }
    grid_barrier();
  }
}

// ---------------- init: weight split/interleave + staging + zeros ----------------
__global__ void init_kernel(
    const float* __restrict__ x,
    const float* __restrict__ eWih0, const float* __restrict__ eWhh0,
    const float* __restrict__ eWih1, const float* __restrict__ eWhh1,
    const float* __restrict__ dWih0, const float* __restrict__ dWhh0,
    const float* __restrict__ dWih1, const float* __restrict__ dWhh1)
{
  const int nthreads = gridDim.x * blockDim.x;
  const int tid0 = blockIdx.x * blockDim.x + threadIdx.x;
  if (tid0 == 0) { g_bar_cnt = 0; g_bar_epoch = 0; }

  // enc0 / dec0 weights: 4096 x P0 pairs
  for (size_t i = tid0; i < (size_t)4096 * P0; i += nthreads) {
    const int c = (int)(i / P0);
    const int p = (int)(i % P0);
    const int orow = (c & 3) * HID + (c >> 2);
    const int k = 2 * p;
    float e0a, e0b, d0a, d0b;
    if (k < 32) {
      e0a = (k < 8) ? eWih0[orow * 8 + k] : 0.f;
      e0b = (k + 1 < 8) ? eWih0[orow * 8 + k + 1] : 0.f;
      d0a = (k == 0) ? dWih0[orow] : 0.f;
      d0b = 0.f;
    } else {
      e0a = eWhh0[(size_t)orow * HID + (k - 32)];
      e0b = eWhh0[(size_t)orow * HID + (k - 31)];
      d0a = dWhh0[(size_t)orow * HID + (k - 32)];
      d0b = dWhh0[(size_t)orow * HID + (k - 31)];
    }
    g_We0[i] = split2(e0a, e0b);
    g_Wd0[i] = split2(d0a, d0b);
  }
  // enc1 / dec1 weights: 4096 x P1 pairs
  for (size_t i = tid0; i < (size_t)4096 * P1; i += nthreads) {
    const int c = (int)(i / P1);
    const int p = (int)(i % P1);
    const int orow = (c & 3) * HID + (c >> 2);
    const int k = 2 * p;
    float e1a, e1b, d1a, d1b;
    if (k < HID) {
      e1a = eWih1[(size_t)orow * HID + k];
      e1b = eWih1[(size_t)orow * HID + k + 1];
      d1a = dWih1[(size_t)orow * HID + k];
      d1b = dWih1[(size_t)orow * HID + k + 1];
    } else {
      e1a = eWhh1[(size_t)orow * HID + (k - HID)];
      e1b = eWhh1[(size_t)orow * HID + (k - HID + 1)];
      d1a = dWhh1[(size_t)orow * HID + (k - HID)];
      d1b = dWhh1[(size_t)orow * HID + (k - HID + 1)];
    }
    g_We1[i] = split2(e1a, e1b);
    g_Wd1[i] = split2(d1a, d1b);
  }
  // x pairs: [t][m][XP]
  for (size_t i = tid0; i < (size_t)TSTEPS * NB * XP; i += nthreads) {
    const int p = (int)(i & (XP - 1));
    const int m = (int)((i >> 4) & (NB - 1));
    const int t = (int)(i >> 11);
    const int k = 2 * p;
    const float v0 = (k < 8) ? x[((size_t)m * TSTEPS + t) * 8 + k] : 0.f;
    const float v1 = (k + 1 < 8) ? x[((size_t)m * TSTEPS + t) * 8 + k + 1] : 0.f;
    g_xp[i] = split2(v0, v1);
  }
  // pred pairs: last x value in slot 0, zeros elsewhere
  for (int i = tid0; i < NB * XP; i += nthreads) {
    const int m = i >> 4;
    const int p = i & (XP - 1);
    g_predp[i] = (p == 0)
        ? split2(x[((size_t)m * TSTEPS + (TSTEPS - 1)) * 8], 0.f)
        : make_uint2(0u, 0u);
  }
  // zero pairs + c states
  for (int i = tid0; i < NB * HP; i += nthreads) g_zerop[i] = make_uint2(0u, 0u);
  for (int i = tid0; i < NB * HID; i += nthreads) { g_c0[i] = 0.f; g_c1[i] = 0.f; }
}

// ---------------- host side ------------------------------------------------------
extern "C" void kernel_launch(void* const* d_in, const int* in_sizes, int n_in,
                              void* d_out, int out_size) {
  const float* x     = (const float*)d_in[0];
  const float* eWih0 = (const float*)d_in[1];
  const float* eWhh0 = (const float*)d_in[2];
  const float* eb0   = (const float*)d_in[3];
  const float* eWih1 = (const float*)d_in[4];
  const float* eWhh1 = (const float*)d_in[5];
  const float* eb1   = (const float*)d_in[6];
  const float* dWih0 = (const float*)d_in[7];
  const float* dWhh0 = (const float*)d_in[8];
  const float* db0   = (const float*)d_in[9];
  const float* dWih1 = (const float*)d_in[10];
  const float* dWhh1 = (const float*)d_in[11];
  const float* db1   = (const float*)d_in[12];
  const float* projW = (const float*)d_in[13];
  const float* projb = (const float*)d_in[14];
  float* out = (float*)d_out;

  init_kernel<<<4096, 512>>>(x, eWih0, eWhh0, eWih1, eWhh1,
                             dWih0, dWhh0, dWih1, dWhh1);
  lstm_persist<<<NCTA, 256>>>(eb0, eb1, db0, db1, projW, projb, out);
}